// round 7
// baseline (speedup 1.0000x reference)
#include <cuda_runtime.h>
#include <cuda_bf16.h>
#include <math.h>
#include <stdint.h>

#define Lc 4
#define Bc 4
#define Nc 2048
#define Dc 512
#define Hc 8
#define HDc 64
#define Mrows (Bc*Nc)   // 8192
#define DD (Dc*Dc)

// ---------------- scratch ----------------
__device__ float g_y[Mrows*Dc];                    // fp32 LN out (FF path)
__device__ float g_t[Mrows*Dc];                    // FF hidden
__device__ float g_wr[2*Lc*DD];                    // tf32-rounded W1,W2
__device__ __nv_bfloat16 g_wt[4*Lc*DD];            // transposed bf16 Wq,Wk,Wv,Wo [n][k]
__device__ __nv_bfloat16 g_yb[Mrows*Dc];           // bf16 LN out (QKV path)
__device__ __nv_bfloat16 g_ob[Mrows*Dc];           // bf16 attention out
__device__ __nv_bfloat16 g_qb[Mrows*Dc];           // Q (pre-scaled, bf16)
__device__ __nv_bfloat16 g_kb[Mrows*Dc];           // K bf16
__device__ __nv_bfloat16 g_vt[Mrows*Dc];           // V bf16, per-(b,h) transposed [64][2048]

__device__ __forceinline__ float rtf32(float x) {
    uint32_t u;
    asm("cvt.rna.tf32.f32 %0, %1;" : "=r"(u) : "f"(x));
    return __uint_as_float(u);
}
__device__ __forceinline__ float gelu_exact(float x) {
    return 0.5f * x * (1.0f + erff(x * 0.70710678118654752f));
}
__device__ __forceinline__ float ex2(float x) {
    float r;
    asm("ex2.approx.f32 %0, %1;" : "=f"(r) : "f"(x));
    return r;
}
__device__ __forceinline__ void cpasync16(void* sdst, const void* gsrc) {
    uint32_t s = (uint32_t)__cvta_generic_to_shared(sdst);
    asm volatile("cp.async.cg.shared.global [%0], [%1], 16;" :: "r"(s), "l"(gsrc));
}
__device__ __forceinline__ void mma_tf32(float* d, const uint32_t* a, const uint32_t* b) {
    asm volatile("mma.sync.aligned.m16n8k8.row.col.f32.tf32.tf32.f32 "
                 "{%0,%1,%2,%3}, {%4,%5,%6,%7}, {%8,%9}, {%0,%1,%2,%3};"
                 : "+f"(d[0]), "+f"(d[1]), "+f"(d[2]), "+f"(d[3])
                 : "r"(a[0]), "r"(a[1]), "r"(a[2]), "r"(a[3]), "r"(b[0]), "r"(b[1]));
}
__device__ __forceinline__ void mma_bf16(float* d, const uint32_t* a, const uint32_t* b) {
    asm volatile("mma.sync.aligned.m16n8k16.row.col.f32.bf16.bf16.f32 "
                 "{%0,%1,%2,%3}, {%4,%5,%6,%7}, {%8,%9}, {%0,%1,%2,%3};"
                 : "+f"(d[0]), "+f"(d[1]), "+f"(d[2]), "+f"(d[3])
                 : "r"(a[0]), "r"(a[1]), "r"(a[2]), "r"(a[3]), "r"(b[0]), "r"(b[1]));
}
__device__ __forceinline__ uint32_t packbf(float lo, float hi) {
    __nv_bfloat162 p = __floats2bfloat162_rn(lo, hi);
    return *(uint32_t*)&p;
}

// ---------------- prep: tf32 rounding (W1,W2) ----------------
__global__ __launch_bounds__(256) void round_kernel(const float* __restrict__ in,
                                                    float* __restrict__ out) {
    const int i = blockIdx.x * 256 + threadIdx.x;
    const float4 v = ((const float4*)in)[i];
    float4 r;
    r.x = rtf32(v.x); r.y = rtf32(v.y); r.z = rtf32(v.z); r.w = rtf32(v.w);
    ((float4*)out)[i] = r;
}

// ---------------- prep: transpose [k][n] fp32 -> [n][k] bf16 ----------------
__global__ __launch_bounds__(256) void transpose_bf16(const float* __restrict__ in,
                                                      __nv_bfloat16* __restrict__ out) {
    __shared__ float t[32][33];
    const int l = blockIdx.z;
    const float* src = in + (long)l * DD;
    __nv_bfloat16* dst = out + (long)l * DD;
    const int n0 = blockIdx.x * 32, k0 = blockIdx.y * 32;
    const int tx = threadIdx.x & 31, ty = threadIdx.x >> 5;
    #pragma unroll
    for (int i = 0; i < 4; i++)
        t[ty + 8 * i][tx] = src[(long)(k0 + ty + 8 * i) * Dc + n0 + tx];
    __syncthreads();
    #pragma unroll
    for (int i = 0; i < 4; i++)
        dst[(long)(n0 + ty + 8 * i) * Dc + k0 + tx] = __float2bfloat16(t[tx][ty + 8 * i]);
}

// ---------------- LayerNorm: BF=1 -> bf16 out, else fp32 (tf32-rounded) ----------------
template <int BF>
__global__ __launch_bounds__(128) void ln_kernel(const float* __restrict__ hin,
                                                 const float* __restrict__ gg,
                                                 const float* __restrict__ bb,
                                                 void* __restrict__ yout) {
    const int row = blockIdx.x;
    const int t = threadIdx.x;
    const float4 v = ((const float4*)(hin + (size_t)row * Dc))[t];
    float s  = v.x + v.y + v.z + v.w;
    float ss = v.x*v.x + v.y*v.y + v.z*v.z + v.w*v.w;
    #pragma unroll
    for (int o = 16; o > 0; o >>= 1) {
        s  += __shfl_xor_sync(0xFFFFFFFFu, s, o);
        ss += __shfl_xor_sync(0xFFFFFFFFu, ss, o);
    }
    __shared__ float sh[8];
    const int w = t >> 5;
    if ((t & 31) == 0) { sh[w] = s; sh[4 + w] = ss; }
    __syncthreads();
    const float st  = sh[0] + sh[1] + sh[2] + sh[3];
    const float sst = sh[4] + sh[5] + sh[6] + sh[7];
    const float mu  = st * (1.0f / Dc);
    const float var = sst * (1.0f / Dc) - mu * mu;
    const float inv = rsqrtf(var + 1e-5f);
    const float4 g4 = ((const float4*)gg)[t];
    const float4 b4 = ((const float4*)bb)[t];
    const float r0 = (v.x - mu) * inv * g4.x + b4.x;
    const float r1 = (v.y - mu) * inv * g4.y + b4.y;
    const float r2 = (v.z - mu) * inv * g4.z + b4.z;
    const float r3 = (v.w - mu) * inv * g4.w + b4.w;
    if (BF) {
        uint2 p;
        p.x = packbf(r0, r1);
        p.y = packbf(r2, r3);
        ((uint2*)((__nv_bfloat16*)yout + (size_t)row * Dc))[t] = p;
    } else {
        float4 r;
        r.x = rtf32(r0); r.y = rtf32(r1); r.z = rtf32(r2); r.w = rtf32(r3);
        ((float4*)((float*)yout + (size_t)row * Dc))[t] = r;
    }
}

struct GemmCtx { int lane, wid, wm, wn, m0, n0; };

// ================= tf32 GEMM mainloop (BM=128, BN=128, BK=32) =================
__device__ __forceinline__ void gemm_mainloop(const float* __restrict__ A, int lda,
                                              const float* __restrict__ Bm, int ldb,
                                              int K, float* smem, GemmCtx& cx,
                                              float acc[2][8][4]) {
    constexpr int BM = 128, BK = 32, BN = 128;
    constexpr int AS = BK + 4, BS = BN + 8;
    float* As = smem;
    float* Bs = smem + 2 * BM * AS;

    const int tid = threadIdx.x;
    cx.lane = tid & 31; cx.wid = tid >> 5;
    cx.wm = (cx.wid >> 1) * 32; cx.wn = (cx.wid & 1) * 64;
    cx.m0 = blockIdx.y * BM; cx.n0 = blockIdx.x * BN;

    const int ar = tid >> 3, ac4 = tid & 7;
    const int br = tid >> 5, bc4 = tid & 31;

    const float* Ag = A + (long)(cx.m0 + ar) * lda + ac4 * 4;
    const float* Bg = Bm + (long)br * ldb + cx.n0 + bc4 * 4;

    #pragma unroll
    for (int mi = 0; mi < 2; mi++)
        #pragma unroll
        for (int ni = 0; ni < 8; ni++)
            #pragma unroll
            for (int j = 0; j < 4; j++) acc[mi][ni][j] = 0.0f;

    const int KT = K / BK;
    {
        #pragma unroll
        for (int i = 0; i < 4; i++)
            cpasync16(&As[(ar + 32 * i) * AS + ac4 * 4], Ag + (long)(32 * i) * lda);
        #pragma unroll
        for (int i = 0; i < 4; i++)
            cpasync16(&Bs[(br + 8 * i) * BS + bc4 * 4], Bg + (long)(8 * i) * ldb);
        asm volatile("cp.async.commit_group;");
    }

    for (int kt = 0; kt < KT; kt++) {
        const int st = kt & 1;
        if (kt + 1 < KT) {
            const int sn = st ^ 1;
            const float* Agn = Ag + (kt + 1) * BK;
            const float* Bgn = Bg + (long)(kt + 1) * BK * ldb;
            #pragma unroll
            for (int i = 0; i < 4; i++)
                cpasync16(&As[sn * BM * AS + (ar + 32 * i) * AS + ac4 * 4],
                          Agn + (long)(32 * i) * lda);
            #pragma unroll
            for (int i = 0; i < 4; i++)
                cpasync16(&Bs[sn * BK * BS + (br + 8 * i) * BS + bc4 * 4],
                          Bgn + (long)(8 * i) * ldb);
            asm volatile("cp.async.commit_group;");
            asm volatile("cp.async.wait_group 1;");
        } else {
            asm volatile("cp.async.wait_group 0;");
        }
        __syncthreads();

        const float* A0 = As + st * BM * AS;
        const float* B0 = Bs + st * BK * BS;
        #pragma unroll
        for (int kk = 0; kk < BK; kk += 8) {
            uint32_t af[2][4];
            #pragma unroll
            for (int mi = 0; mi < 2; mi++) {
                const int r = cx.wm + mi * 16 + (cx.lane >> 2);
                const int c = kk + (cx.lane & 3);
                af[mi][0] = __float_as_uint(A0[r * AS + c]);
                af[mi][1] = __float_as_uint(A0[(r + 8) * AS + c]);
                af[mi][2] = __float_as_uint(A0[r * AS + c + 4]);
                af[mi][3] = __float_as_uint(A0[(r + 8) * AS + c + 4]);
            }
            uint32_t bf[8][2];
            #pragma unroll
            for (int ni = 0; ni < 8; ni++) {
                const int col = cx.wn + ni * 8 + (cx.lane >> 2);
                const int kr = kk + (cx.lane & 3);
                bf[ni][0] = __float_as_uint(B0[kr * BS + col]);
                bf[ni][1] = __float_as_uint(B0[(kr + 4) * BS + col]);
            }
            #pragma unroll
            for (int mi = 0; mi < 2; mi++)
                #pragma unroll
                for (int ni = 0; ni < 8; ni++)
                    mma_tf32(acc[mi][ni], af[mi], bf[ni]);
        }
        __syncthreads();
    }
}

// ================= bf16 GEMM mainloop (BM=128, BN=128, BK=32) =================
// A row-major [m][k] bf16, B pre-transposed [n][k] bf16 (both k-contiguous).
__device__ __forceinline__ void bf16_mainloop(const __nv_bfloat16* __restrict__ A,
                                              const __nv_bfloat16* __restrict__ Bt,
                                              uint32_t* smw, GemmCtx& cx,
                                              float acc[2][8][4]) {
    constexpr int RW = 20;  // words per smem row (32 bf16 + 8 pad)
    uint32_t* As = smw;                 // [2][128][20]
    uint32_t* Bs = smw + 2 * 128 * RW;  // [2][128][20]

    const int tid = threadIdx.x;
    cx.lane = tid & 31; cx.wid = tid >> 5;
    cx.wm = (cx.wid >> 1) * 32; cx.wn = (cx.wid & 1) * 64;
    cx.m0 = blockIdx.y * 128; cx.n0 = blockIdx.x * 128;

    #pragma unroll
    for (int mi = 0; mi < 2; mi++)
        #pragma unroll
        for (int ni = 0; ni < 8; ni++)
            #pragma unroll
            for (int j = 0; j < 4; j++) acc[mi][ni][j] = 0.0f;

    // loader: 512 chunks of 16B per tile -> 2 per thread
    const int r0l = (tid) >> 2, ch0 = (tid & 3);
    const int r1l = (tid + 256) >> 2, ch1 = ((tid + 256) & 3);

    const __nv_bfloat16* Ag = A + (long)cx.m0 * Dc;
    const __nv_bfloat16* Bg = Bt + (long)cx.n0 * Dc;

    {
        cpasync16(&As[r0l * RW + ch0 * 4], Ag + (long)r0l * Dc + ch0 * 8);
        cpasync16(&As[r1l * RW + ch1 * 4], Ag + (long)r1l * Dc + ch1 * 8);
        cpasync16(&Bs[r0l * RW + ch0 * 4], Bg + (long)r0l * Dc + ch0 * 8);
        cpasync16(&Bs[r1l * RW + ch1 * 4], Bg + (long)r1l * Dc + ch1 * 8);
        asm volatile("cp.async.commit_group;");
    }

    const int KT = Dc / 32;
    for (int kt = 0; kt < KT; kt++) {
        const int st = kt & 1;
        if (kt + 1 < KT) {
            const int sn = st ^ 1;
            const int ko = (kt + 1) * 32;
            cpasync16(&As[sn * 128 * RW + r0l * RW + ch0 * 4], Ag + (long)r0l * Dc + ko + ch0 * 8);
            cpasync16(&As[sn * 128 * RW + r1l * RW + ch1 * 4], Ag + (long)r1l * Dc + ko + ch1 * 8);
            cpasync16(&Bs[sn * 128 * RW + r0l * RW + ch0 * 4], Bg + (long)r0l * Dc + ko + ch0 * 8);
            cpasync16(&Bs[sn * 128 * RW + r1l * RW + ch1 * 4], Bg + (long)r1l * Dc + ko + ch1 * 8);
            asm volatile("cp.async.commit_group;");
            asm volatile("cp.async.wait_group 1;");
        } else {
            asm volatile("cp.async.wait_group 0;");
        }
        __syncthreads();

        const uint32_t* A0 = As + st * 128 * RW;
        const uint32_t* B0 = Bs + st * 128 * RW;
        #pragma unroll
        for (int s = 0; s < 2; s++) {
            uint32_t af[2][4];
            #pragma unroll
            for (int mi = 0; mi < 2; mi++) {
                const int r = cx.wm + mi * 16 + (cx.lane >> 2);
                const int c = s * 8 + (cx.lane & 3);
                af[mi][0] = A0[r * RW + c];
                af[mi][1] = A0[(r + 8) * RW + c];
                af[mi][2] = A0[r * RW + c + 4];
                af[mi][3] = A0[(r + 8) * RW + c + 4];
            }
            uint32_t bf[8][2];
            #pragma unroll
            for (int ni = 0; ni < 8; ni++) {
                const int n = cx.wn + ni * 8 + (cx.lane >> 2);
                const int c = s * 8 + (cx.lane & 3);
                bf[ni][0] = B0[n * RW + c];
                bf[ni][1] = B0[n * RW + c + 4];
            }
            #pragma unroll
            for (int mi = 0; mi < 2; mi++)
                #pragma unroll
                for (int ni = 0; ni < 8; ni++)
                    mma_bf16(acc[mi][ni], af[mi], bf[ni]);
        }
        __syncthreads();
    }
}

// ---------------- tf32 GEMM with fp32 epilogue (FF path) ----------------
// OP 1: C = resid + acc + bias ; OP 2: C = gelu(acc + bias)
template <int OP, int RND>
__global__ __launch_bounds__(256)
void gemm_pipe(const float* __restrict__ A, const float* __restrict__ Bm,
               float* __restrict__ C,
               const float* __restrict__ bias, const float* __restrict__ resid) {
    extern __shared__ float smem[];
    GemmCtx cx;
    float acc[2][8][4];
    gemm_mainloop(A, Dc, Bm, Dc, Dc, smem, cx, acc);

    #pragma unroll
    for (int mi = 0; mi < 2; mi++) {
        const int r0 = cx.m0 + cx.wm + mi * 16 + (cx.lane >> 2);
        #pragma unroll
        for (int ni = 0; ni < 8; ni++) {
            const int col = cx.n0 + cx.wn + ni * 8 + (cx.lane & 3) * 2;
            #pragma unroll
            for (int half = 0; half < 2; half++) {
                const int r = r0 + half * 8;
                float v0 = acc[mi][ni][half * 2 + 0];
                float v1 = acc[mi][ni][half * 2 + 1];
                if (OP == 1) {
                    const float2 rs = *(const float2*)(resid + (long)r * Dc + col);
                    v0 = rs.x + v0 + bias[col];
                    v1 = rs.y + v1 + bias[col + 1];
                } else {
                    v0 = gelu_exact(v0 + bias[col]);
                    v1 = gelu_exact(v1 + bias[col + 1]);
                }
                if (RND) { v0 = rtf32(v0); v1 = rtf32(v1); }
                float2 w2; w2.x = v0; w2.y = v1;
                *(float2*)(C + (long)r * Dc + col) = w2;
            }
        }
    }
}

// ---------------- QKV bf16 GEMM: z selects weight + output layout ----------------
#define QSC 0.06376237f  /* 512^-0.5 * log2(e) */
__global__ __launch_bounds__(256)
void qkv_gemm(const __nv_bfloat16* __restrict__ A, const __nv_bfloat16* __restrict__ wqt,
              const __nv_bfloat16* __restrict__ wkt, const __nv_bfloat16* __restrict__ wvt) {
    extern __shared__ uint32_t smw[];
    const int z = blockIdx.z;
    const __nv_bfloat16* W = (z == 0) ? wqt : (z == 1) ? wkt : wvt;
    GemmCtx cx;
    float acc[2][8][4];
    bf16_mainloop(A, W, smw, cx, acc);

    #pragma unroll
    for (int mi = 0; mi < 2; mi++) {
        const int r0 = cx.m0 + cx.wm + mi * 16 + (cx.lane >> 2);
        #pragma unroll
        for (int ni = 0; ni < 8; ni++) {
            const int col = cx.n0 + cx.wn + ni * 8 + (cx.lane & 3) * 2;
            #pragma unroll
            for (int half = 0; half < 2; half++) {
                const int r = r0 + half * 8;
                const float v0 = acc[mi][ni][half * 2 + 0];
                const float v1 = acc[mi][ni][half * 2 + 1];
                if (z == 0) {
                    *(uint32_t*)(g_qb + (long)r * Dc + col) = packbf(v0 * QSC, v1 * QSC);
                } else if (z == 1) {
                    *(uint32_t*)(g_kb + (long)r * Dc + col) = packbf(v0, v1);
                } else {
                    const int bidx = r >> 11, tok = r & 2047;
                    const long hb = ((long)bidx * Hc + (col >> 6)) * (HDc * Nc);
                    g_vt[hb + (long)(col & 63) * Nc + tok] = __float2bfloat16(v0);
                    g_vt[hb + (long)((col + 1) & 63) * Nc + tok] = __float2bfloat16(v1);
                }
            }
        }
    }
}

// ---------------- Wo bf16 GEMM: h = resid + o@Wo + bias ----------------
__global__ __launch_bounds__(256)
void wo_gemm(const __nv_bfloat16* __restrict__ A, const __nv_bfloat16* __restrict__ wot,
             float* __restrict__ C, const float* __restrict__ bias,
             const float* __restrict__ resid) {
    extern __shared__ uint32_t smw[];
    GemmCtx cx;
    float acc[2][8][4];
    bf16_mainloop(A, wot, smw, cx, acc);

    #pragma unroll
    for (int mi = 0; mi < 2; mi++) {
        const int r0 = cx.m0 + cx.wm + mi * 16 + (cx.lane >> 2);
        #pragma unroll
        for (int ni = 0; ni < 8; ni++) {
            const int col = cx.n0 + cx.wn + ni * 8 + (cx.lane & 3) * 2;
            #pragma unroll
            for (int half = 0; half < 2; half++) {
                const int r = r0 + half * 8;
                const float2 rs = *(const float2*)(resid + (long)r * Dc + col);
                float2 w2;
                w2.x = rs.x + acc[mi][ni][half * 2 + 0] + bias[col];
                w2.y = rs.y + acc[mi][ni][half * 2 + 1] + bias[col + 1];
                *(float2*)(C + (long)r * Dc + col) = w2;
            }
        }
    }
}

// ---------------- bf16 fused flash attention ----------------
__global__ __launch_bounds__(256, 2) void fattn_kernel() {
    constexpr int QS = 72;
    extern __shared__ __align__(16) char smraw[];
    __nv_bfloat16* Qs = (__nv_bfloat16*)smraw;      // [128][72]
    __nv_bfloat16* Ks = Qs + 128 * QS;              // [2][64][72]
    __nv_bfloat16* Vt = Ks + 2 * 64 * QS;           // [2][64][72] (dim-major)

    const int qt = blockIdx.x, hh = blockIdx.y, bb = blockIdx.z;
    const int tid = threadIdx.x, lane = tid & 31, wid = tid >> 5;
    const long kvbase = ((long)bb * Nc) * Dc + hh * HDc;
    const long vtbase = ((long)bb * Hc + hh) * (HDc * Nc);

    #pragma unroll
    for (int i = 0; i < 4; i++) {
        const int idx = tid + 256 * i;
        const int r = idx >> 3, ch = idx & 7;
        cpasync16(&Qs[r * QS + ch * 8],
                  g_qb + kvbase + (long)(qt * 128 + r) * Dc + ch * 8);
    }
    #pragma unroll
    for (int i = 0; i < 2; i++) {
        const int idx = tid + 256 * i;
        const int r = idx >> 3, ch = idx & 7;
        cpasync16(&Ks[r * QS + ch * 8], g_kb + kvbase + (long)r * Dc + ch * 8);
        cpasync16(&Vt[r * QS + ch * 8], g_vt + vtbase + (long)r * Nc + ch * 8);
    }
    asm volatile("cp.async.commit_group;");
    asm volatile("cp.async.wait_group 0;");
    __syncthreads();

    uint32_t qf[4][4];
    {
        const uint32_t* Qw = (const uint32_t*)Qs;
        const int r0 = wid * 16 + (lane >> 2);
        #pragma unroll
        for (int ka = 0; ka < 4; ka++) {
            const int c = ka * 8 + (lane & 3);
            qf[ka][0] = Qw[r0 * 36 + c];
            qf[ka][1] = Qw[(r0 + 8) * 36 + c];
            qf[ka][2] = Qw[r0 * 36 + c + 4];
            qf[ka][3] = Qw[(r0 + 8) * 36 + c + 4];
        }
    }

    float o[8][4];
    #pragma unroll
    for (int d = 0; d < 8; d++)
        #pragma unroll
        for (int j = 0; j < 4; j++) o[d][j] = 0.0f;
    float m0 = -1e30f, m1 = -1e30f, l0 = 0.0f, l1 = 0.0f;

    for (int kt = 0; kt < Nc / 64; kt++) {
        const int st = kt & 1;
        if (kt + 1 < Nc / 64) {
            const int sn = st ^ 1;
            #pragma unroll
            for (int i = 0; i < 2; i++) {
                const int idx = tid + 256 * i;
                const int r = idx >> 3, ch = idx & 7;
                cpasync16(&Ks[sn * 64 * QS + r * QS + ch * 8],
                          g_kb + kvbase + (long)((kt + 1) * 64 + r) * Dc + ch * 8);
                cpasync16(&Vt[sn * 64 * QS + r * QS + ch * 8],
                          g_vt + vtbase + (long)r * Nc + (kt + 1) * 64 + ch * 8);
            }
            asm volatile("cp.async.commit_group;");
            asm volatile("cp.async.wait_group 1;");
        } else {
            asm volatile("cp.async.wait_group 0;");
        }
        __syncthreads();

        const uint32_t* Kw = (const uint32_t*)(Ks + st * 64 * QS);
        const uint32_t* Vw = (const uint32_t*)(Vt + st * 64 * QS);

        float sc[8][4];
        #pragma unroll
        for (int j = 0; j < 8; j++) {
            #pragma unroll
            for (int i = 0; i < 4; i++) sc[j][i] = 0.0f;
            const int n = j * 8 + (lane >> 2);
            #pragma unroll
            for (int ka = 0; ka < 4; ka++) {
                uint32_t b[2];
                b[0] = Kw[n * 36 + ka * 8 + (lane & 3)];
                b[1] = Kw[n * 36 + ka * 8 + 4 + (lane & 3)];
                mma_bf16(sc[j], qf[ka], b);
            }
        }

        float tm0 = -1e30f, tm1 = -1e30f;
        #pragma unroll
        for (int j = 0; j < 8; j++) {
            tm0 = fmaxf(tm0, fmaxf(sc[j][0], sc[j][1]));
            tm1 = fmaxf(tm1, fmaxf(sc[j][2], sc[j][3]));
        }
        tm0 = fmaxf(tm0, __shfl_xor_sync(0xFFFFFFFFu, tm0, 1));
        tm0 = fmaxf(tm0, __shfl_xor_sync(0xFFFFFFFFu, tm0, 2));
        tm1 = fmaxf(tm1, __shfl_xor_sync(0xFFFFFFFFu, tm1, 1));
        tm1 = fmaxf(tm1, __shfl_xor_sync(0xFFFFFFFFu, tm1, 2));
        const float nm0 = fmaxf(m0, tm0), nm1 = fmaxf(m1, tm1);
        const float c0 = ex2(m0 - nm0), c1 = ex2(m1 - nm1);
        m0 = nm0; m1 = nm1; l0 *= c0; l1 *= c1;
        #pragma unroll
        for (int j = 0; j < 8; j++) {
            sc[j][0] = ex2(sc[j][0] - m0);
            sc[j][1] = ex2(sc[j][1] - m0);
            sc[j][2] = ex2(sc[j][2] - m1);
            sc[j][3] = ex2(sc[j][3] - m1);
            l0 += sc[j][0] + sc[j][1];
            l1 += sc[j][2] + sc[j][3];
        }
        #pragma unroll
        for (int d = 0; d < 8; d++) {
            o[d][0] *= c0; o[d][1] *= c0; o[d][2] *= c1; o[d][3] *= c1;
        }

        #pragma unroll
        for (int s = 0; s < 4; s++) {
            uint32_t a[4];
            a[0] = packbf(sc[2 * s][0], sc[2 * s][1]);
            a[1] = packbf(sc[2 * s][2], sc[2 * s][3]);
            a[2] = packbf(sc[2 * s + 1][0], sc[2 * s + 1][1]);
            a[3] = packbf(sc[2 * s + 1][2], sc[2 * s + 1][3]);
            #pragma unroll
            for (int d = 0; d < 8; d++) {
                const int col = d * 8 + (lane >> 2);
                uint32_t b[2];
                b[0] = Vw[col * 36 + s * 8 + (lane & 3)];
                b[1] = Vw[col * 36 + s * 8 + 4 + (lane & 3)];
                mma_bf16(o[d], a, b);
            }
        }
        __syncthreads();
    }

    l0 += __shfl_xor_sync(0xFFFFFFFFu, l0, 1);
    l0 += __shfl_xor_sync(0xFFFFFFFFu, l0, 2);
    l1 += __shfl_xor_sync(0xFFFFFFFFu, l1, 1);
    l1 += __shfl_xor_sync(0xFFFFFFFFu, l1, 2);
    const float i0 = 1.0f / l0, i1 = 1.0f / l1;

    const int r0 = qt * 128 + wid * 16 + (lane >> 2);
    __nv_bfloat16* op0 = g_ob + ((long)bb * Nc) * Dc + hh * HDc + (long)r0 * Dc;
    __nv_bfloat16* op1 = op0 + 8 * Dc;
    #pragma unroll
    for (int d = 0; d < 8; d++) {
        const int col = d * 8 + 2 * (lane & 3);
        *(uint32_t*)(op0 + col) = packbf(o[d][0] * i0, o[d][1] * i0);
        *(uint32_t*)(op1 + col) = packbf(o[d][2] * i1, o[d][3] * i1);
    }
}

// ---------------- driver ----------------
extern "C" void kernel_launch(void* const* d_in, const int* in_sizes, int n_in,
                              void* d_out, int out_size) {
    const float* x    = (const float*)d_in[0];
    const float* Wq   = (const float*)d_in[1];
    const float* Wk   = (const float*)d_in[2];
    const float* Wv   = (const float*)d_in[3];
    const float* Wo   = (const float*)d_in[4];
    const float* bo   = (const float*)d_in[5];
    const float* ln1g = (const float*)d_in[6];
    const float* ln1b = (const float*)d_in[7];
    const float* W1   = (const float*)d_in[8];
    const float* b1   = (const float*)d_in[9];
    const float* W2   = (const float*)d_in[10];
    const float* b2   = (const float*)d_in[11];
    const float* ln2g = (const float*)d_in[12];
    const float* ln2b = (const float*)d_in[13];
    float* h = (float*)d_out;

    float *py, *pt, *pw;
    __nv_bfloat16 *pwt, *pyb, *pob;
    cudaGetSymbolAddress((void**)&py, g_y);
    cudaGetSymbolAddress((void**)&pt, g_t);
    cudaGetSymbolAddress((void**)&pw, g_wr);
    cudaGetSymbolAddress((void**)&pwt, g_wt);
    cudaGetSymbolAddress((void**)&pyb, g_yb);
    cudaGetSymbolAddress((void**)&pob, g_ob);

    const int smemProj = (2 * 128 * 36 + 2 * 32 * 136) * 4;  // 71680
    const int smemBF   = 4 * 128 * 20 * 4;                   // 40960
    const int smemAttn = (128 * 72 + 4 * 64 * 72) * 2;       // 55296
    cudaFuncSetAttribute(gemm_pipe<1, 0>, cudaFuncAttributeMaxDynamicSharedMemorySize, smemProj);
    cudaFuncSetAttribute(gemm_pipe<2, 1>, cudaFuncAttributeMaxDynamicSharedMemorySize, smemProj);
    cudaFuncSetAttribute(fattn_kernel, cudaFuncAttributeMaxDynamicSharedMemorySize, smemAttn);

    cudaMemcpyAsync(h, x, sizeof(float) * (size_t)Mrows * Dc, cudaMemcpyDeviceToDevice);

    // prep: round FF weights to tf32; transpose attention weights to bf16 [n][k]
    const int WSZ = Lc * DD;
    round_kernel<<<WSZ / 1024, 256>>>(W1, pw + 0L * WSZ);
    round_kernel<<<WSZ / 1024, 256>>>(W2, pw + 1L * WSZ);
    const dim3 gT(Dc / 32, Dc / 32, Lc);
    transpose_bf16<<<gT, 256>>>(Wq, pwt + 0L * WSZ);
    transpose_bf16<<<gT, 256>>>(Wk, pwt + 1L * WSZ);
    transpose_bf16<<<gT, 256>>>(Wv, pwt + 2L * WSZ);
    transpose_bf16<<<gT, 256>>>(Wo, pwt + 3L * WSZ);

    const dim3 gProj(Dc / 128, Mrows / 128, 1);     // (4, 64)
    const dim3 gQKV(Dc / 128, Mrows / 128, 3);      // (4, 64, 3)
    const dim3 gAttn(Nc / 128, Hc, Bc);             // (16, 8, 4)

    for (int l = 0; l < Lc; l++) {
        const __nv_bfloat16* wqt = pwt + 0L * WSZ + (long)l * DD;
        const __nv_bfloat16* wkt = pwt + 1L * WSZ + (long)l * DD;
        const __nv_bfloat16* wvt = pwt + 2L * WSZ + (long)l * DD;
        const __nv_bfloat16* wot = pwt + 3L * WSZ + (long)l * DD;
        const float* w1 = pw + 0L * WSZ + (long)l * DD;
        const float* w2 = pw + 1L * WSZ + (long)l * DD;

        ln_kernel<1><<<Mrows, 128>>>(h, ln1g + l * Dc, ln1b + l * Dc, pyb);
        qkv_gemm<<<gQKV, 256, smemBF>>>(pyb, wqt, wkt, wvt);
        fattn_kernel<<<gAttn, 256, smemAttn>>>();
        wo_gemm<<<gProj, 256, smemBF>>>(pob, wot, h, bo + l * Dc, h);
        ln_kernel<0><<<Mrows, 128>>>(h, ln2g + l * Dc, ln2b + l * Dc, py);
        gemm_pipe<2, 1><<<gProj, 256, smemProj>>>(py, w1, pt, b1 + l * Dc, nullptr);
        gemm_pipe<1, 0><<<gProj, 256, smemProj>>>(pt, w2, h, b2 + l * Dc, h);
    }
}

// round 8
// speedup vs baseline: 1.0815x; 1.0815x over previous
#include <cuda_runtime.h>
#include <cuda_bf16.h>
#include <math.h>
#include <stdint.h>

#define Lc 4
#define Bc 4
#define Nc 2048
#define Dc 512
#define Hc 8
#define HDc 64
#define Mrows (Bc*Nc)   // 8192
#define DD (Dc*Dc)

// ---------------- scratch ----------------
__device__ __nv_bfloat16 g_wt[6*Lc*DD];            // transposed bf16 weights [n][k]
__device__ __nv_bfloat16 g_yb[Mrows*Dc];           // bf16 LN out
__device__ __nv_bfloat16 g_tb[Mrows*Dc];           // bf16 FF hidden
__device__ __nv_bfloat16 g_ob[Mrows*Dc];           // bf16 attention out
__device__ __nv_bfloat16 g_qb[Mrows*Dc];           // Q (pre-scaled, bf16)
__device__ __nv_bfloat16 g_kb[Mrows*Dc];           // K bf16
__device__ __nv_bfloat16 g_vt[Mrows*Dc];           // V bf16, per-(b,h) transposed [64][2048]

__device__ __forceinline__ float gelu_exact(float x) {
    return 0.5f * x * (1.0f + erff(x * 0.70710678118654752f));
}
__device__ __forceinline__ float ex2(float x) {
    float r;
    asm("ex2.approx.f32 %0, %1;" : "=f"(r) : "f"(x));
    return r;
}
__device__ __forceinline__ void cpasync16(void* sdst, const void* gsrc) {
    uint32_t s = (uint32_t)__cvta_generic_to_shared(sdst);
    asm volatile("cp.async.cg.shared.global [%0], [%1], 16;" :: "r"(s), "l"(gsrc));
}
__device__ __forceinline__ void mma_bf16(float* d, const uint32_t* a, const uint32_t* b) {
    asm volatile("mma.sync.aligned.m16n8k16.row.col.f32.bf16.bf16.f32 "
                 "{%0,%1,%2,%3}, {%4,%5,%6,%7}, {%8,%9}, {%0,%1,%2,%3};"
                 : "+f"(d[0]), "+f"(d[1]), "+f"(d[2]), "+f"(d[3])
                 : "r"(a[0]), "r"(a[1]), "r"(a[2]), "r"(a[3]), "r"(b[0]), "r"(b[1]));
}
__device__ __forceinline__ uint32_t packbf(float lo, float hi) {
    __nv_bfloat162 p = __floats2bfloat162_rn(lo, hi);
    return *(uint32_t*)&p;
}

// ---------------- prep: transpose [k][n] fp32 -> [n][k] bf16 ----------------
__global__ __launch_bounds__(256) void transpose_bf16(const float* __restrict__ in,
                                                      __nv_bfloat16* __restrict__ out) {
    __shared__ float t[32][33];
    const int l = blockIdx.z;
    const float* src = in + (long)l * DD;
    __nv_bfloat16* dst = out + (long)l * DD;
    const int n0 = blockIdx.x * 32, k0 = blockIdx.y * 32;
    const int tx = threadIdx.x & 31, ty = threadIdx.x >> 5;
    #pragma unroll
    for (int i = 0; i < 4; i++)
        t[ty + 8 * i][tx] = src[(long)(k0 + ty + 8 * i) * Dc + n0 + tx];
    __syncthreads();
    #pragma unroll
    for (int i = 0; i < 4; i++)
        dst[(long)(n0 + ty + 8 * i) * Dc + k0 + tx] = __float2bfloat16(t[tx][ty + 8 * i]);
}

// ---------------- LayerNorm -> bf16 ----------------
__global__ __launch_bounds__(128) void ln_kernel(const float* __restrict__ hin,
                                                 const float* __restrict__ gg,
                                                 const float* __restrict__ bb,
                                                 __nv_bfloat16* __restrict__ yout) {
    const int row = blockIdx.x;
    const int t = threadIdx.x;
    const float4 v = ((const float4*)(hin + (size_t)row * Dc))[t];
    float s  = v.x + v.y + v.z + v.w;
    float ss = v.x*v.x + v.y*v.y + v.z*v.z + v.w*v.w;
    #pragma unroll
    for (int o = 16; o > 0; o >>= 1) {
        s  += __shfl_xor_sync(0xFFFFFFFFu, s, o);
        ss += __shfl_xor_sync(0xFFFFFFFFu, ss, o);
    }
    __shared__ float sh[8];
    const int w = t >> 5;
    if ((t & 31) == 0) { sh[w] = s; sh[4 + w] = ss; }
    __syncthreads();
    const float st  = sh[0] + sh[1] + sh[2] + sh[3];
    const float sst = sh[4] + sh[5] + sh[6] + sh[7];
    const float mu  = st * (1.0f / Dc);
    const float var = sst * (1.0f / Dc) - mu * mu;
    const float inv = rsqrtf(var + 1e-5f);
    const float4 g4 = ((const float4*)gg)[t];
    const float4 b4 = ((const float4*)bb)[t];
    uint2 p;
    p.x = packbf((v.x - mu) * inv * g4.x + b4.x, (v.y - mu) * inv * g4.y + b4.y);
    p.y = packbf((v.z - mu) * inv * g4.z + b4.z, (v.w - mu) * inv * g4.w + b4.w);
    ((uint2*)(yout + (size_t)row * Dc))[t] = p;
}

struct GemmCtx { int lane, wid, wm, wn, m0, n0; };

// ================= bf16 GEMM mainloop (BM=128, BN=128, BK=32) =================
// A row-major [m][k] bf16, B pre-transposed [n][k] bf16 (both k-contiguous).
__device__ __forceinline__ void bf16_mainloop(const __nv_bfloat16* __restrict__ A,
                                              const __nv_bfloat16* __restrict__ Bt,
                                              uint32_t* smw, GemmCtx& cx,
                                              float acc[2][8][4]) {
    constexpr int RW = 20;  // words per smem row (32 bf16 + 8 pad)
    uint32_t* As = smw;                 // [2][128][20]
    uint32_t* Bs = smw + 2 * 128 * RW;  // [2][128][20]

    const int tid = threadIdx.x;
    cx.lane = tid & 31; cx.wid = tid >> 5;
    cx.wm = (cx.wid >> 1) * 32; cx.wn = (cx.wid & 1) * 64;
    cx.m0 = blockIdx.y * 128; cx.n0 = blockIdx.x * 128;

    #pragma unroll
    for (int mi = 0; mi < 2; mi++)
        #pragma unroll
        for (int ni = 0; ni < 8; ni++)
            #pragma unroll
            for (int j = 0; j < 4; j++) acc[mi][ni][j] = 0.0f;

    const int r0l = (tid) >> 2, ch0 = (tid & 3);
    const int r1l = (tid + 256) >> 2, ch1 = ((tid + 256) & 3);

    const __nv_bfloat16* Ag = A + (long)cx.m0 * Dc;
    const __nv_bfloat16* Bg = Bt + (long)cx.n0 * Dc;

    {
        cpasync16(&As[r0l * RW + ch0 * 4], Ag + (long)r0l * Dc + ch0 * 8);
        cpasync16(&As[r1l * RW + ch1 * 4], Ag + (long)r1l * Dc + ch1 * 8);
        cpasync16(&Bs[r0l * RW + ch0 * 4], Bg + (long)r0l * Dc + ch0 * 8);
        cpasync16(&Bs[r1l * RW + ch1 * 4], Bg + (long)r1l * Dc + ch1 * 8);
        asm volatile("cp.async.commit_group;");
    }

    const int KT = Dc / 32;
    for (int kt = 0; kt < KT; kt++) {
        const int st = kt & 1;
        if (kt + 1 < KT) {
            const int sn = st ^ 1;
            const int ko = (kt + 1) * 32;
            cpasync16(&As[sn * 128 * RW + r0l * RW + ch0 * 4], Ag + (long)r0l * Dc + ko + ch0 * 8);
            cpasync16(&As[sn * 128 * RW + r1l * RW + ch1 * 4], Ag + (long)r1l * Dc + ko + ch1 * 8);
            cpasync16(&Bs[sn * 128 * RW + r0l * RW + ch0 * 4], Bg + (long)r0l * Dc + ko + ch0 * 8);
            cpasync16(&Bs[sn * 128 * RW + r1l * RW + ch1 * 4], Bg + (long)r1l * Dc + ko + ch1 * 8);
            asm volatile("cp.async.commit_group;");
            asm volatile("cp.async.wait_group 1;");
        } else {
            asm volatile("cp.async.wait_group 0;");
        }
        __syncthreads();

        const uint32_t* A0 = As + st * 128 * RW;
        const uint32_t* B0 = Bs + st * 128 * RW;
        #pragma unroll
        for (int s = 0; s < 2; s++) {
            uint32_t af[2][4];
            #pragma unroll
            for (int mi = 0; mi < 2; mi++) {
                const int r = cx.wm + mi * 16 + (cx.lane >> 2);
                const int c = s * 8 + (cx.lane & 3);
                af[mi][0] = A0[r * RW + c];
                af[mi][1] = A0[(r + 8) * RW + c];
                af[mi][2] = A0[r * RW + c + 4];
                af[mi][3] = A0[(r + 8) * RW + c + 4];
            }
            uint32_t bf[8][2];
            #pragma unroll
            for (int ni = 0; ni < 8; ni++) {
                const int n = cx.wn + ni * 8 + (cx.lane >> 2);
                const int c = s * 8 + (cx.lane & 3);
                bf[ni][0] = B0[n * RW + c];
                bf[ni][1] = B0[n * RW + c + 4];
            }
            #pragma unroll
            for (int mi = 0; mi < 2; mi++)
                #pragma unroll
                for (int ni = 0; ni < 8; ni++)
                    mma_bf16(acc[mi][ni], af[mi], bf[ni]);
        }
        __syncthreads();
    }
}

// ---------------- QKV bf16 GEMM: z selects weight + output layout ----------------
#define QSC 0.06376237f  /* 512^-0.5 * log2(e) */
__global__ __launch_bounds__(256)
void qkv_gemm(const __nv_bfloat16* __restrict__ A, const __nv_bfloat16* __restrict__ wqt,
              const __nv_bfloat16* __restrict__ wkt, const __nv_bfloat16* __restrict__ wvt) {
    extern __shared__ uint32_t smw[];
    const int z = blockIdx.z;
    const __nv_bfloat16* W = (z == 0) ? wqt : (z == 1) ? wkt : wvt;
    GemmCtx cx;
    float acc[2][8][4];
    bf16_mainloop(A, W, smw, cx, acc);

    #pragma unroll
    for (int mi = 0; mi < 2; mi++) {
        const int r0 = cx.m0 + cx.wm + mi * 16 + (cx.lane >> 2);
        #pragma unroll
        for (int ni = 0; ni < 8; ni++) {
            const int col = cx.n0 + cx.wn + ni * 8 + (cx.lane & 3) * 2;
            #pragma unroll
            for (int half = 0; half < 2; half++) {
                const int r = r0 + half * 8;
                const float v0 = acc[mi][ni][half * 2 + 0];
                const float v1 = acc[mi][ni][half * 2 + 1];
                if (z == 0) {
                    *(uint32_t*)(g_qb + (long)r * Dc + col) = packbf(v0 * QSC, v1 * QSC);
                } else if (z == 1) {
                    *(uint32_t*)(g_kb + (long)r * Dc + col) = packbf(v0, v1);
                } else {
                    const int bidx = r >> 11, tok = r & 2047;
                    const long hb = ((long)bidx * Hc + (col >> 6)) * (HDc * Nc);
                    g_vt[hb + (long)(col & 63) * Nc + tok] = __float2bfloat16(v0);
                    g_vt[hb + (long)((col + 1) & 63) * Nc + tok] = __float2bfloat16(v1);
                }
            }
        }
    }
}

// ---------------- residual bf16 GEMM: C = resid + A@Wt + bias (fp32 out) ----------------
__global__ __launch_bounds__(256)
void resid_gemm(const __nv_bfloat16* __restrict__ A, const __nv_bfloat16* __restrict__ Wt,
                float* __restrict__ C, const float* __restrict__ bias,
                const float* __restrict__ resid) {
    extern __shared__ uint32_t smw[];
    GemmCtx cx;
    float acc[2][8][4];
    bf16_mainloop(A, Wt, smw, cx, acc);

    #pragma unroll
    for (int mi = 0; mi < 2; mi++) {
        const int r0 = cx.m0 + cx.wm + mi * 16 + (cx.lane >> 2);
        #pragma unroll
        for (int ni = 0; ni < 8; ni++) {
            const int col = cx.n0 + cx.wn + ni * 8 + (cx.lane & 3) * 2;
            #pragma unroll
            for (int half = 0; half < 2; half++) {
                const int r = r0 + half * 8;
                const float2 rs = *(const float2*)(resid + (long)r * Dc + col);
                float2 w2;
                w2.x = rs.x + acc[mi][ni][half * 2 + 0] + bias[col];
                w2.y = rs.y + acc[mi][ni][half * 2 + 1] + bias[col + 1];
                *(float2*)(C + (long)r * Dc + col) = w2;
            }
        }
    }
}

// ---------------- gelu bf16 GEMM: C = gelu(A@Wt + bias) (bf16 out) ----------------
__global__ __launch_bounds__(256)
void gelu_gemm(const __nv_bfloat16* __restrict__ A, const __nv_bfloat16* __restrict__ Wt,
               __nv_bfloat16* __restrict__ C, const float* __restrict__ bias) {
    extern __shared__ uint32_t smw[];
    GemmCtx cx;
    float acc[2][8][4];
    bf16_mainloop(A, Wt, smw, cx, acc);

    #pragma unroll
    for (int mi = 0; mi < 2; mi++) {
        const int r0 = cx.m0 + cx.wm + mi * 16 + (cx.lane >> 2);
        #pragma unroll
        for (int ni = 0; ni < 8; ni++) {
            const int col = cx.n0 + cx.wn + ni * 8 + (cx.lane & 3) * 2;
            #pragma unroll
            for (int half = 0; half < 2; half++) {
                const int r = r0 + half * 8;
                const float v0 = gelu_exact(acc[mi][ni][half * 2 + 0] + bias[col]);
                const float v1 = gelu_exact(acc[mi][ni][half * 2 + 1] + bias[col + 1]);
                *(uint32_t*)(C + (long)r * Dc + col) = packbf(v0, v1);
            }
        }
    }
}

// ---------------- bf16 fused flash attention ----------------
__global__ __launch_bounds__(256, 2) void fattn_kernel() {
    constexpr int QS = 72;
    extern __shared__ __align__(16) char smraw[];
    __nv_bfloat16* Qs = (__nv_bfloat16*)smraw;      // [128][72]
    __nv_bfloat16* Ks = Qs + 128 * QS;              // [2][64][72]
    __nv_bfloat16* Vt = Ks + 2 * 64 * QS;           // [2][64][72] (dim-major)

    const int qt = blockIdx.x, hh = blockIdx.y, bb = blockIdx.z;
    const int tid = threadIdx.x, lane = tid & 31, wid = tid >> 5;
    const long kvbase = ((long)bb * Nc) * Dc + hh * HDc;
    const long vtbase = ((long)bb * Hc + hh) * (HDc * Nc);

    #pragma unroll
    for (int i = 0; i < 4; i++) {
        const int idx = tid + 256 * i;
        const int r = idx >> 3, ch = idx & 7;
        cpasync16(&Qs[r * QS + ch * 8],
                  g_qb + kvbase + (long)(qt * 128 + r) * Dc + ch * 8);
    }
    #pragma unroll
    for (int i = 0; i < 2; i++) {
        const int idx = tid + 256 * i;
        const int r = idx >> 3, ch = idx & 7;
        cpasync16(&Ks[r * QS + ch * 8], g_kb + kvbase + (long)r * Dc + ch * 8);
        cpasync16(&Vt[r * QS + ch * 8], g_vt + vtbase + (long)r * Nc + ch * 8);
    }
    asm volatile("cp.async.commit_group;");
    asm volatile("cp.async.wait_group 0;");
    __syncthreads();

    uint32_t qf[4][4];
    {
        const uint32_t* Qw = (const uint32_t*)Qs;
        const int r0 = wid * 16 + (lane >> 2);
        #pragma unroll
        for (int ka = 0; ka < 4; ka++) {
            const int c = ka * 8 + (lane & 3);
            qf[ka][0] = Qw[r0 * 36 + c];
            qf[ka][1] = Qw[(r0 + 8) * 36 + c];
            qf[ka][2] = Qw[r0 * 36 + c + 4];
            qf[ka][3] = Qw[(r0 + 8) * 36 + c + 4];
        }
    }

    float o[8][4];
    #pragma unroll
    for (int d = 0; d < 8; d++)
        #pragma unroll
        for (int j = 0; j < 4; j++) o[d][j] = 0.0f;
    float m0 = -1e30f, m1 = -1e30f, l0 = 0.0f, l1 = 0.0f;

    for (int kt = 0; kt < Nc / 64; kt++) {
        const int st = kt & 1;
        if (kt + 1 < Nc / 64) {
            const int sn = st ^ 1;
            #pragma unroll
            for (int i = 0; i < 2; i++) {
                const int idx = tid + 256 * i;
                const int r = idx >> 3, ch = idx & 7;
                cpasync16(&Ks[sn * 64 * QS + r * QS + ch * 8],
                          g_kb + kvbase + (long)((kt + 1) * 64 + r) * Dc + ch * 8);
                cpasync16(&Vt[sn * 64 * QS + r * QS + ch * 8],
                          g_vt + vtbase + (long)r * Nc + (kt + 1) * 64 + ch * 8);
            }
            asm volatile("cp.async.commit_group;");
            asm volatile("cp.async.wait_group 1;");
        } else {
            asm volatile("cp.async.wait_group 0;");
        }
        __syncthreads();

        const uint32_t* Kw = (const uint32_t*)(Ks + st * 64 * QS);
        const uint32_t* Vw = (const uint32_t*)(Vt + st * 64 * QS);

        float sc[8][4];
        #pragma unroll
        for (int j = 0; j < 8; j++) {
            #pragma unroll
            for (int i = 0; i < 4; i++) sc[j][i] = 0.0f;
            const int n = j * 8 + (lane >> 2);
            #pragma unroll
            for (int ka = 0; ka < 4; ka++) {
                uint32_t b[2];
                b[0] = Kw[n * 36 + ka * 8 + (lane & 3)];
                b[1] = Kw[n * 36 + ka * 8 + 4 + (lane & 3)];
                mma_bf16(sc[j], qf[ka], b);
            }
        }

        float tm0 = -1e30f, tm1 = -1e30f;
        #pragma unroll
        for (int j = 0; j < 8; j++) {
            tm0 = fmaxf(tm0, fmaxf(sc[j][0], sc[j][1]));
            tm1 = fmaxf(tm1, fmaxf(sc[j][2], sc[j][3]));
        }
        tm0 = fmaxf(tm0, __shfl_xor_sync(0xFFFFFFFFu, tm0, 1));
        tm0 = fmaxf(tm0, __shfl_xor_sync(0xFFFFFFFFu, tm0, 2));
        tm1 = fmaxf(tm1, __shfl_xor_sync(0xFFFFFFFFu, tm1, 1));
        tm1 = fmaxf(tm1, __shfl_xor_sync(0xFFFFFFFFu, tm1, 2));
        const float nm0 = fmaxf(m0, tm0), nm1 = fmaxf(m1, tm1);
        const float c0 = ex2(m0 - nm0), c1 = ex2(m1 - nm1);
        m0 = nm0; m1 = nm1; l0 *= c0; l1 *= c1;
        #pragma unroll
        for (int j = 0; j < 8; j++) {
            sc[j][0] = ex2(sc[j][0] - m0);
            sc[j][1] = ex2(sc[j][1] - m0);
            sc[j][2] = ex2(sc[j][2] - m1);
            sc[j][3] = ex2(sc[j][3] - m1);
            l0 += sc[j][0] + sc[j][1];
            l1 += sc[j][2] + sc[j][3];
        }
        #pragma unroll
        for (int d = 0; d < 8; d++) {
            o[d][0] *= c0; o[d][1] *= c0; o[d][2] *= c1; o[d][3] *= c1;
        }

        #pragma unroll
        for (int s = 0; s < 4; s++) {
            uint32_t a[4];
            a[0] = packbf(sc[2 * s][0], sc[2 * s][1]);
            a[1] = packbf(sc[2 * s][2], sc[2 * s][3]);
            a[2] = packbf(sc[2 * s + 1][0], sc[2 * s + 1][1]);
            a[3] = packbf(sc[2 * s + 1][2], sc[2 * s + 1][3]);
            #pragma unroll
            for (int d = 0; d < 8; d++) {
                const int col = d * 8 + (lane >> 2);
                uint32_t b[2];
                b[0] = Vw[col * 36 + s * 8 + (lane & 3)];
                b[1] = Vw[col * 36 + s * 8 + 4 + (lane & 3)];
                mma_bf16(o[d], a, b);
            }
        }
        __syncthreads();
    }

    l0 += __shfl_xor_sync(0xFFFFFFFFu, l0, 1);
    l0 += __shfl_xor_sync(0xFFFFFFFFu, l0, 2);
    l1 += __shfl_xor_sync(0xFFFFFFFFu, l1, 1);
    l1 += __shfl_xor_sync(0xFFFFFFFFu, l1, 2);
    const float i0 = 1.0f / l0, i1 = 1.0f / l1;

    const int r0 = qt * 128 + wid * 16 + (lane >> 2);
    __nv_bfloat16* op0 = g_ob + ((long)bb * Nc) * Dc + hh * HDc + (long)r0 * Dc;
    __nv_bfloat16* op1 = op0 + 8 * Dc;
    #pragma unroll
    for (int d = 0; d < 8; d++) {
        const int col = d * 8 + 2 * (lane & 3);
        *(uint32_t*)(op0 + col) = packbf(o[d][0] * i0, o[d][1] * i0);
        *(uint32_t*)(op1 + col) = packbf(o[d][2] * i1, o[d][3] * i1);
    }
}

// ---------------- driver ----------------
extern "C" void kernel_launch(void* const* d_in, const int* in_sizes, int n_in,
                              void* d_out, int out_size) {
    const float* x    = (const float*)d_in[0];
    const float* Wq   = (const float*)d_in[1];
    const float* Wk   = (const float*)d_in[2];
    const float* Wv   = (const float*)d_in[3];
    const float* Wo   = (const float*)d_in[4];
    const float* bo   = (const float*)d_in[5];
    const float* ln1g = (const float*)d_in[6];
    const float* ln1b = (const float*)d_in[7];
    const float* W1   = (const float*)d_in[8];
    const float* b1   = (const float*)d_in[9];
    const float* W2   = (const float*)d_in[10];
    const float* b2   = (const float*)d_in[11];
    const float* ln2g = (const float*)d_in[12];
    const float* ln2b = (const float*)d_in[13];
    float* h = (float*)d_out;

    __nv_bfloat16 *pwt, *pyb, *ptb, *pob;
    cudaGetSymbolAddress((void**)&pwt, g_wt);
    cudaGetSymbolAddress((void**)&pyb, g_yb);
    cudaGetSymbolAddress((void**)&ptb, g_tb);
    cudaGetSymbolAddress((void**)&pob, g_ob);

    const int smemBF   = 4 * 128 * 20 * 4;                   // 40960
    const int smemAttn = (128 * 72 + 4 * 64 * 72) * 2;       // 55296
    cudaFuncSetAttribute(fattn_kernel, cudaFuncAttributeMaxDynamicSharedMemorySize, smemAttn);

    cudaMemcpyAsync(h, x, sizeof(float) * (size_t)Mrows * Dc, cudaMemcpyDeviceToDevice);

    // prep: transpose all weights to bf16 [n][k]
    const int WSZ = Lc * DD;
    const dim3 gT(Dc / 32, Dc / 32, Lc);
    transpose_bf16<<<gT, 256>>>(Wq, pwt + 0L * WSZ);
    transpose_bf16<<<gT, 256>>>(Wk, pwt + 1L * WSZ);
    transpose_bf16<<<gT, 256>>>(Wv, pwt + 2L * WSZ);
    transpose_bf16<<<gT, 256>>>(Wo, pwt + 3L * WSZ);
    transpose_bf16<<<gT, 256>>>(W1, pwt + 4L * WSZ);
    transpose_bf16<<<gT, 256>>>(W2, pwt + 5L * WSZ);

    const dim3 gProj(Dc / 128, Mrows / 128, 1);     // (4, 64)
    const dim3 gQKV(Dc / 128, Mrows / 128, 3);      // (4, 64, 3)
    const dim3 gAttn(Nc / 128, Hc, Bc);             // (16, 8, 4)

    for (int l = 0; l < Lc; l++) {
        const __nv_bfloat16* wqt = pwt + 0L * WSZ + (long)l * DD;
        const __nv_bfloat16* wkt = pwt + 1L * WSZ + (long)l * DD;
        const __nv_bfloat16* wvt = pwt + 2L * WSZ + (long)l * DD;
        const __nv_bfloat16* wot = pwt + 3L * WSZ + (long)l * DD;
        const __nv_bfloat16* w1t = pwt + 4L * WSZ + (long)l * DD;
        const __nv_bfloat16* w2t = pwt + 5L * WSZ + (long)l * DD;

        ln_kernel<<<Mrows, 128>>>(h, ln1g + l * Dc, ln1b + l * Dc, pyb);
        qkv_gemm<<<gQKV, 256, smemBF>>>(pyb, wqt, wkt, wvt);
        fattn_kernel<<<gAttn, 256, smemAttn>>>();
        resid_gemm<<<gProj, 256, smemBF>>>(pob, wot, h, bo + l * Dc, h);
        ln_kernel<<<Mrows, 128>>>(h, ln2g + l * Dc, ln2b + l * Dc, pyb);
        gelu_gemm<<<gProj, 256, smemBF>>>(pyb, w1t, ptb, b1 + l * Dc);
        resid_gemm<<<gProj, 256, smemBF>>>(ptb, w2t, h, b2 + l * Dc, h);
    }
}

// round 9
// speedup vs baseline: 1.0818x; 1.0003x over previous
#include <cuda_runtime.h>
#include <cuda_bf16.h>
#include <math.h>
#include <stdint.h>

#define Lc 4
#define Bc 4
#define Nc 2048
#define Dc 512
#define Hc 8
#define HDc 64
#define Mrows (Bc*Nc)   // 8192
#define DD (Dc*Dc)

// ---------------- scratch ----------------
__device__ __nv_bfloat16 g_wt[6*Lc*DD];            // transposed bf16 weights [n][k]
__device__ __nv_bfloat16 g_yb[Mrows*Dc];           // bf16 LN out
__device__ __nv_bfloat16 g_tb[Mrows*Dc];           // bf16 FF hidden
__device__ __nv_bfloat16 g_ob[Mrows*Dc];           // bf16 attention out
__device__ __nv_bfloat16 g_qb[Mrows*Dc];           // Q (pre-scaled, bf16)
__device__ __nv_bfloat16 g_kb[Mrows*Dc];           // K bf16
__device__ __nv_bfloat16 g_vt[Mrows*Dc];           // V bf16, per-(b,h) transposed [64][2048]

__device__ __forceinline__ float gelu_exact(float x) {
    return 0.5f * x * (1.0f + erff(x * 0.70710678118654752f));
}
__device__ __forceinline__ float ex2(float x) {
    float r;
    asm("ex2.approx.f32 %0, %1;" : "=f"(r) : "f"(x));
    return r;
}
__device__ __forceinline__ void cpasync16(void* sdst, const void* gsrc) {
    uint32_t s = (uint32_t)__cvta_generic_to_shared(sdst);
    asm volatile("cp.async.cg.shared.global [%0], [%1], 16;" :: "r"(s), "l"(gsrc));
}
__device__ __forceinline__ void mma_bf16(float* d, const uint32_t* a, const uint32_t* b) {
    asm volatile("mma.sync.aligned.m16n8k16.row.col.f32.bf16.bf16.f32 "
                 "{%0,%1,%2,%3}, {%4,%5,%6,%7}, {%8,%9}, {%0,%1,%2,%3};"
                 : "+f"(d[0]), "+f"(d[1]), "+f"(d[2]), "+f"(d[3])
                 : "r"(a[0]), "r"(a[1]), "r"(a[2]), "r"(a[3]), "r"(b[0]), "r"(b[1]));
}
__device__ __forceinline__ uint32_t packbf(float lo, float hi) {
    __nv_bfloat162 p = __floats2bfloat162_rn(lo, hi);
    return *(uint32_t*)&p;
}

// ---------------- prep: transpose [k][n] fp32 -> [n][k] bf16 ----------------
__global__ __launch_bounds__(256) void transpose_bf16(const float* __restrict__ in,
                                                      __nv_bfloat16* __restrict__ out) {
    __shared__ float t[32][33];
    const int l = blockIdx.z;
    const float* src = in + (long)l * DD;
    __nv_bfloat16* dst = out + (long)l * DD;
    const int n0 = blockIdx.x * 32, k0 = blockIdx.y * 32;
    const int tx = threadIdx.x & 31, ty = threadIdx.x >> 5;
    #pragma unroll
    for (int i = 0; i < 4; i++)
        t[ty + 8 * i][tx] = src[(long)(k0 + ty + 8 * i) * Dc + n0 + tx];
    __syncthreads();
    #pragma unroll
    for (int i = 0; i < 4; i++)
        dst[(long)(n0 + ty + 8 * i) * Dc + k0 + tx] = __float2bfloat16(t[tx][ty + 8 * i]);
}

// ---------------- LayerNorm -> bf16 ----------------
__global__ __launch_bounds__(128) void ln_kernel(const float* __restrict__ hin,
                                                 const float* __restrict__ gg,
                                                 const float* __restrict__ bb,
                                                 __nv_bfloat16* __restrict__ yout) {
    const int row = blockIdx.x;
    const int t = threadIdx.x;
    const float4 v = ((const float4*)(hin + (size_t)row * Dc))[t];
    float s  = v.x + v.y + v.z + v.w;
    float ss = v.x*v.x + v.y*v.y + v.z*v.z + v.w*v.w;
    #pragma unroll
    for (int o = 16; o > 0; o >>= 1) {
        s  += __shfl_xor_sync(0xFFFFFFFFu, s, o);
        ss += __shfl_xor_sync(0xFFFFFFFFu, ss, o);
    }
    __shared__ float sh[8];
    const int w = t >> 5;
    if ((t & 31) == 0) { sh[w] = s; sh[4 + w] = ss; }
    __syncthreads();
    const float st  = sh[0] + sh[1] + sh[2] + sh[3];
    const float sst = sh[4] + sh[5] + sh[6] + sh[7];
    const float mu  = st * (1.0f / Dc);
    const float var = sst * (1.0f / Dc) - mu * mu;
    const float inv = rsqrtf(var + 1e-5f);
    const float4 g4 = ((const float4*)gg)[t];
    const float4 b4 = ((const float4*)bb)[t];
    uint2 p;
    p.x = packbf((v.x - mu) * inv * g4.x + b4.x, (v.y - mu) * inv * g4.y + b4.y);
    p.y = packbf((v.z - mu) * inv * g4.z + b4.z, (v.w - mu) * inv * g4.w + b4.w);
    ((uint2*)(yout + (size_t)row * Dc))[t] = p;
}

struct GemmCtx { int lane, wid, wm, wn, m0, n0; };

// ================= bf16 GEMM mainloop (BM=128, BN=128, BK=32) =================
// A row-major [m][k] bf16, B pre-transposed [n][k] bf16 (both k-contiguous).
__device__ __forceinline__ void bf16_mainloop(const __nv_bfloat16* __restrict__ A,
                                              const __nv_bfloat16* __restrict__ Bt,
                                              uint32_t* smw, GemmCtx& cx,
                                              float acc[2][8][4]) {
    constexpr int RW = 20;  // words per smem row (32 bf16 + 8 pad)
    uint32_t* As = smw;                 // [2][128][20]
    uint32_t* Bs = smw + 2 * 128 * RW;  // [2][128][20]

    const int tid = threadIdx.x;
    cx.lane = tid & 31; cx.wid = tid >> 5;
    cx.wm = (cx.wid >> 1) * 32; cx.wn = (cx.wid & 1) * 64;
    cx.m0 = blockIdx.y * 128; cx.n0 = blockIdx.x * 128;

    #pragma unroll
    for (int mi = 0; mi < 2; mi++)
        #pragma unroll
        for (int ni = 0; ni < 8; ni++)
            #pragma unroll
            for (int j = 0; j < 4; j++) acc[mi][ni][j] = 0.0f;

    const int r0l = (tid) >> 2, ch0 = (tid & 3);
    const int r1l = (tid + 256) >> 2, ch1 = ((tid + 256) & 3);

    const __nv_bfloat16* Ag = A + (long)cx.m0 * Dc;
    const __nv_bfloat16* Bg = Bt + (long)cx.n0 * Dc;

    {
        cpasync16(&As[r0l * RW + ch0 * 4], Ag + (long)r0l * Dc + ch0 * 8);
        cpasync16(&As[r1l * RW + ch1 * 4], Ag + (long)r1l * Dc + ch1 * 8);
        cpasync16(&Bs[r0l * RW + ch0 * 4], Bg + (long)r0l * Dc + ch0 * 8);
        cpasync16(&Bs[r1l * RW + ch1 * 4], Bg + (long)r1l * Dc + ch1 * 8);
        asm volatile("cp.async.commit_group;");
    }

    const int KT = Dc / 32;
    for (int kt = 0; kt < KT; kt++) {
        const int st = kt & 1;
        if (kt + 1 < KT) {
            const int sn = st ^ 1;
            const int ko = (kt + 1) * 32;
            cpasync16(&As[sn * 128 * RW + r0l * RW + ch0 * 4], Ag + (long)r0l * Dc + ko + ch0 * 8);
            cpasync16(&As[sn * 128 * RW + r1l * RW + ch1 * 4], Ag + (long)r1l * Dc + ko + ch1 * 8);
            cpasync16(&Bs[sn * 128 * RW + r0l * RW + ch0 * 4], Bg + (long)r0l * Dc + ko + ch0 * 8);
            cpasync16(&Bs[sn * 128 * RW + r1l * RW + ch1 * 4], Bg + (long)r1l * Dc + ko + ch1 * 8);
            asm volatile("cp.async.commit_group;");
            asm volatile("cp.async.wait_group 1;");
        } else {
            asm volatile("cp.async.wait_group 0;");
        }
        __syncthreads();

        const uint32_t* A0 = As + st * 128 * RW;
        const uint32_t* B0 = Bs + st * 128 * RW;
        #pragma unroll
        for (int s = 0; s < 2; s++) {
            uint32_t af[2][4];
            #pragma unroll
            for (int mi = 0; mi < 2; mi++) {
                const int r = cx.wm + mi * 16 + (cx.lane >> 2);
                const int c = s * 8 + (cx.lane & 3);
                af[mi][0] = A0[r * RW + c];
                af[mi][1] = A0[(r + 8) * RW + c];
                af[mi][2] = A0[r * RW + c + 4];
                af[mi][3] = A0[(r + 8) * RW + c + 4];
            }
            uint32_t bf[8][2];
            #pragma unroll
            for (int ni = 0; ni < 8; ni++) {
                const int n = cx.wn + ni * 8 + (cx.lane >> 2);
                const int c = s * 8 + (cx.lane & 3);
                bf[ni][0] = B0[n * RW + c];
                bf[ni][1] = B0[n * RW + c + 4];
            }
            #pragma unroll
            for (int mi = 0; mi < 2; mi++)
                #pragma unroll
                for (int ni = 0; ni < 8; ni++)
                    mma_bf16(acc[mi][ni], af[mi], bf[ni]);
        }
        __syncthreads();
    }
}

// ---------------- QKV bf16 GEMM: z selects weight + output layout ----------------
#define QSC 0.06376237f  /* 512^-0.5 * log2(e) */
__global__ __launch_bounds__(256)
void qkv_gemm(const __nv_bfloat16* __restrict__ A, const __nv_bfloat16* __restrict__ wqt,
              const __nv_bfloat16* __restrict__ wkt, const __nv_bfloat16* __restrict__ wvt) {
    extern __shared__ uint32_t smw[];
    const int z = blockIdx.z;
    const __nv_bfloat16* W = (z == 0) ? wqt : (z == 1) ? wkt : wvt;
    GemmCtx cx;
    float acc[2][8][4];
    bf16_mainloop(A, W, smw, cx, acc);

    #pragma unroll
    for (int mi = 0; mi < 2; mi++) {
        const int r0 = cx.m0 + cx.wm + mi * 16 + (cx.lane >> 2);
        #pragma unroll
        for (int ni = 0; ni < 8; ni++) {
            const int col = cx.n0 + cx.wn + ni * 8 + (cx.lane & 3) * 2;
            #pragma unroll
            for (int half = 0; half < 2; half++) {
                const int r = r0 + half * 8;
                const float v0 = acc[mi][ni][half * 2 + 0];
                const float v1 = acc[mi][ni][half * 2 + 1];
                if (z == 0) {
                    *(uint32_t*)(g_qb + (long)r * Dc + col) = packbf(v0 * QSC, v1 * QSC);
                } else if (z == 1) {
                    *(uint32_t*)(g_kb + (long)r * Dc + col) = packbf(v0, v1);
                } else {
                    const int bidx = r >> 11, tok = r & 2047;
                    const long hb = ((long)bidx * Hc + (col >> 6)) * (HDc * Nc);
                    g_vt[hb + (long)(col & 63) * Nc + tok] = __float2bfloat16(v0);
                    g_vt[hb + (long)((col + 1) & 63) * Nc + tok] = __float2bfloat16(v1);
                }
            }
        }
    }
}

// ---------------- residual bf16 GEMM: C = resid + A@Wt + bias (fp32 out) ----------------
__global__ __launch_bounds__(256)
void resid_gemm(const __nv_bfloat16* __restrict__ A, const __nv_bfloat16* __restrict__ Wt,
                float* __restrict__ C, const float* __restrict__ bias,
                const float* __restrict__ resid) {
    extern __shared__ uint32_t smw[];
    GemmCtx cx;
    float acc[2][8][4];
    bf16_mainloop(A, Wt, smw, cx, acc);

    #pragma unroll
    for (int mi = 0; mi < 2; mi++) {
        const int r0 = cx.m0 + cx.wm + mi * 16 + (cx.lane >> 2);
        #pragma unroll
        for (int ni = 0; ni < 8; ni++) {
            const int col = cx.n0 + cx.wn + ni * 8 + (cx.lane & 3) * 2;
            #pragma unroll
            for (int half = 0; half < 2; half++) {
                const int r = r0 + half * 8;
                const float2 rs = *(const float2*)(resid + (long)r * Dc + col);
                float2 w2;
                w2.x = rs.x + acc[mi][ni][half * 2 + 0] + bias[col];
                w2.y = rs.y + acc[mi][ni][half * 2 + 1] + bias[col + 1];
                *(float2*)(C + (long)r * Dc + col) = w2;
            }
        }
    }
}

// ---------------- gelu bf16 GEMM: C = gelu(A@Wt + bias) (bf16 out) ----------------
__global__ __launch_bounds__(256)
void gelu_gemm(const __nv_bfloat16* __restrict__ A, const __nv_bfloat16* __restrict__ Wt,
               __nv_bfloat16* __restrict__ C, const float* __restrict__ bias) {
    extern __shared__ uint32_t smw[];
    GemmCtx cx;
    float acc[2][8][4];
    bf16_mainloop(A, Wt, smw, cx, acc);

    #pragma unroll
    for (int mi = 0; mi < 2; mi++) {
        const int r0 = cx.m0 + cx.wm + mi * 16 + (cx.lane >> 2);
        #pragma unroll
        for (int ni = 0; ni < 8; ni++) {
            const int col = cx.n0 + cx.wn + ni * 8 + (cx.lane & 3) * 2;
            #pragma unroll
            for (int half = 0; half < 2; half++) {
                const int r = r0 + half * 8;
                const float v0 = gelu_exact(acc[mi][ni][half * 2 + 0] + bias[col]);
                const float v1 = gelu_exact(acc[mi][ni][half * 2 + 1] + bias[col + 1]);
                *(uint32_t*)(C + (long)r * Dc + col) = packbf(v0, v1);
            }
        }
    }
}

// ---------------- bf16 fused flash attention ----------------
__global__ __launch_bounds__(256, 2) void fattn_kernel() {
    constexpr int QS = 72;
    extern __shared__ __align__(16) char smraw[];
    __nv_bfloat16* Qs = (__nv_bfloat16*)smraw;      // [128][72]
    __nv_bfloat16* Ks = Qs + 128 * QS;              // [2][64][72]
    __nv_bfloat16* Vt = Ks + 2 * 64 * QS;           // [2][64][72] (dim-major)

    const int qt = blockIdx.x, hh = blockIdx.y, bb = blockIdx.z;
    const int tid = threadIdx.x, lane = tid & 31, wid = tid >> 5;
    const long kvbase = ((long)bb * Nc) * Dc + hh * HDc;
    const long vtbase = ((long)bb * Hc + hh) * (HDc * Nc);

    #pragma unroll
    for (int i = 0; i < 4; i++) {
        const int idx = tid + 256 * i;
        const int r = idx >> 3, ch = idx & 7;
        cpasync16(&Qs[r * QS + ch * 8],
                  g_qb + kvbase + (long)(qt * 128 + r) * Dc + ch * 8);
    }
    #pragma unroll
    for (int i = 0; i < 2; i++) {
        const int idx = tid + 256 * i;
        const int r = idx >> 3, ch = idx & 7;
        cpasync16(&Ks[r * QS + ch * 8], g_kb + kvbase + (long)r * Dc + ch * 8);
        cpasync16(&Vt[r * QS + ch * 8], g_vt + vtbase + (long)r * Nc + ch * 8);
    }
    asm volatile("cp.async.commit_group;");
    asm volatile("cp.async.wait_group 0;");
    __syncthreads();

    uint32_t qf[4][4];
    {
        const uint32_t* Qw = (const uint32_t*)Qs;
        const int r0 = wid * 16 + (lane >> 2);
        #pragma unroll
        for (int ka = 0; ka < 4; ka++) {
            const int c = ka * 8 + (lane & 3);
            qf[ka][0] = Qw[r0 * 36 + c];
            qf[ka][1] = Qw[(r0 + 8) * 36 + c];
            qf[ka][2] = Qw[r0 * 36 + c + 4];
            qf[ka][3] = Qw[(r0 + 8) * 36 + c + 4];
        }
    }

    float o[8][4];
    #pragma unroll
    for (int d = 0; d < 8; d++)
        #pragma unroll
        for (int j = 0; j < 4; j++) o[d][j] = 0.0f;
    float m0 = -1e30f, m1 = -1e30f, l0 = 0.0f, l1 = 0.0f;

    for (int kt = 0; kt < Nc / 64; kt++) {
        const int st = kt & 1;
        if (kt + 1 < Nc / 64) {
            const int sn = st ^ 1;
            #pragma unroll
            for (int i = 0; i < 2; i++) {
                const int idx = tid + 256 * i;
                const int r = idx >> 3, ch = idx & 7;
                cpasync16(&Ks[sn * 64 * QS + r * QS + ch * 8],
                          g_kb + kvbase + (long)((kt + 1) * 64 + r) * Dc + ch * 8);
                cpasync16(&Vt[sn * 64 * QS + r * QS + ch * 8],
                          g_vt + vtbase + (long)r * Nc + (kt + 1) * 64 + ch * 8);
            }
            asm volatile("cp.async.commit_group;");
            asm volatile("cp.async.wait_group 1;");
        } else {
            asm volatile("cp.async.wait_group 0;");
        }
        __syncthreads();

        const uint32_t* Kw = (const uint32_t*)(Ks + st * 64 * QS);
        const uint32_t* Vw = (const uint32_t*)(Vt + st * 64 * QS);

        float sc[8][4];
        #pragma unroll
        for (int j = 0; j < 8; j++) {
            #pragma unroll
            for (int i = 0; i < 4; i++) sc[j][i] = 0.0f;
            const int n = j * 8 + (lane >> 2);
            #pragma unroll
            for (int ka = 0; ka < 4; ka++) {
                uint32_t b[2];
                b[0] = Kw[n * 36 + ka * 8 + (lane & 3)];
                b[1] = Kw[n * 36 + ka * 8 + 4 + (lane & 3)];
                mma_bf16(sc[j], qf[ka], b);
            }
        }

        float tm0 = -1e30f, tm1 = -1e30f;
        #pragma unroll
        for (int j = 0; j < 8; j++) {
            tm0 = fmaxf(tm0, fmaxf(sc[j][0], sc[j][1]));
            tm1 = fmaxf(tm1, fmaxf(sc[j][2], sc[j][3]));
        }
        tm0 = fmaxf(tm0, __shfl_xor_sync(0xFFFFFFFFu, tm0, 1));
        tm0 = fmaxf(tm0, __shfl_xor_sync(0xFFFFFFFFu, tm0, 2));
        tm1 = fmaxf(tm1, __shfl_xor_sync(0xFFFFFFFFu, tm1, 1));
        tm1 = fmaxf(tm1, __shfl_xor_sync(0xFFFFFFFFu, tm1, 2));
        const float nm0 = fmaxf(m0, tm0), nm1 = fmaxf(m1, tm1);
        const float c0 = ex2(m0 - nm0), c1 = ex2(m1 - nm1);
        m0 = nm0; m1 = nm1; l0 *= c0; l1 *= c1;
        #pragma unroll
        for (int j = 0; j < 8; j++) {
            sc[j][0] = ex2(sc[j][0] - m0);
            sc[j][1] = ex2(sc[j][1] - m0);
            sc[j][2] = ex2(sc[j][2] - m1);
            sc[j][3] = ex2(sc[j][3] - m1);
            l0 += sc[j][0] + sc[j][1];
            l1 += sc[j][2] + sc[j][3];
        }
        #pragma unroll
        for (int d = 0; d < 8; d++) {
            o[d][0] *= c0; o[d][1] *= c0; o[d][2] *= c1; o[d][3] *= c1;
        }

        #pragma unroll
        for (int s = 0; s < 4; s++) {
            uint32_t a[4];
            a[0] = packbf(sc[2 * s][0], sc[2 * s][1]);
            a[1] = packbf(sc[2 * s][2], sc[2 * s][3]);
            a[2] = packbf(sc[2 * s + 1][0], sc[2 * s + 1][1]);
            a[3] = packbf(sc[2 * s + 1][2], sc[2 * s + 1][3]);
            #pragma unroll
            for (int d = 0; d < 8; d++) {
                const int col = d * 8 + (lane >> 2);
                uint32_t b[2];
                b[0] = Vw[col * 36 + s * 8 + (lane & 3)];
                b[1] = Vw[col * 36 + s * 8 + 4 + (lane & 3)];
                mma_bf16(o[d], a, b);
            }
        }
        __syncthreads();
    }

    l0 += __shfl_xor_sync(0xFFFFFFFFu, l0, 1);
    l0 += __shfl_xor_sync(0xFFFFFFFFu, l0, 2);
    l1 += __shfl_xor_sync(0xFFFFFFFFu, l1, 1);
    l1 += __shfl_xor_sync(0xFFFFFFFFu, l1, 2);
    const float i0 = 1.0f / l0, i1 = 1.0f / l1;

    const int r0 = qt * 128 + wid * 16 + (lane >> 2);
    __nv_bfloat16* op0 = g_ob + ((long)bb * Nc) * Dc + hh * HDc + (long)r0 * Dc;
    __nv_bfloat16* op1 = op0 + 8 * Dc;
    #pragma unroll
    for (int d = 0; d < 8; d++) {
        const int col = d * 8 + 2 * (lane & 3);
        *(uint32_t*)(op0 + col) = packbf(o[d][0] * i0, o[d][1] * i0);
        *(uint32_t*)(op1 + col) = packbf(o[d][2] * i1, o[d][3] * i1);
    }
}

// ---------------- driver ----------------
extern "C" void kernel_launch(void* const* d_in, const int* in_sizes, int n_in,
                              void* d_out, int out_size) {
    const float* x    = (const float*)d_in[0];
    const float* Wq   = (const float*)d_in[1];
    const float* Wk   = (const float*)d_in[2];
    const float* Wv   = (const float*)d_in[3];
    const float* Wo   = (const float*)d_in[4];
    const float* bo   = (const float*)d_in[5];
    const float* ln1g = (const float*)d_in[6];
    const float* ln1b = (const float*)d_in[7];
    const float* W1   = (const float*)d_in[8];
    const float* b1   = (const float*)d_in[9];
    const float* W2   = (const float*)d_in[10];
    const float* b2   = (const float*)d_in[11];
    const float* ln2g = (const float*)d_in[12];
    const float* ln2b = (const float*)d_in[13];
    float* h = (float*)d_out;

    __nv_bfloat16 *pwt, *pyb, *ptb, *pob;
    cudaGetSymbolAddress((void**)&pwt, g_wt);
    cudaGetSymbolAddress((void**)&pyb, g_yb);
    cudaGetSymbolAddress((void**)&ptb, g_tb);
    cudaGetSymbolAddress((void**)&pob, g_ob);

    const int smemBF   = 4 * 128 * 20 * 4;                   // 40960
    const int smemAttn = (128 * 72 + 4 * 64 * 72) * 2;       // 55296
    cudaFuncSetAttribute(fattn_kernel, cudaFuncAttributeMaxDynamicSharedMemorySize, smemAttn);

    cudaMemcpyAsync(h, x, sizeof(float) * (size_t)Mrows * Dc, cudaMemcpyDeviceToDevice);

    // prep: transpose all weights to bf16 [n][k]
    const int WSZ = Lc * DD;
    const dim3 gT(Dc / 32, Dc / 32, Lc);
    transpose_bf16<<<gT, 256>>>(Wq, pwt + 0L * WSZ);
    transpose_bf16<<<gT, 256>>>(Wk, pwt + 1L * WSZ);
    transpose_bf16<<<gT, 256>>>(Wv, pwt + 2L * WSZ);
    transpose_bf16<<<gT, 256>>>(Wo, pwt + 3L * WSZ);
    transpose_bf16<<<gT, 256>>>(W1, pwt + 4L * WSZ);
    transpose_bf16<<<gT, 256>>>(W2, pwt + 5L * WSZ);

    const dim3 gProj(Dc / 128, Mrows / 128, 1);     // (4, 64)
    const dim3 gQKV(Dc / 128, Mrows / 128, 3);      // (4, 64, 3)
    const dim3 gAttn(Nc / 128, Hc, Bc);             // (16, 8, 4)

    for (int l = 0; l < Lc; l++) {
        const __nv_bfloat16* wqt = pwt + 0L * WSZ + (long)l * DD;
        const __nv_bfloat16* wkt = pwt + 1L * WSZ + (long)l * DD;
        const __nv_bfloat16* wvt = pwt + 2L * WSZ + (long)l * DD;
        const __nv_bfloat16* wot = pwt + 3L * WSZ + (long)l * DD;
        const __nv_bfloat16* w1t = pwt + 4L * WSZ + (long)l * DD;
        const __nv_bfloat16* w2t = pwt + 5L * WSZ + (long)l * DD;

        ln_kernel<<<Mrows, 128>>>(h, ln1g + l * Dc, ln1b + l * Dc, pyb);
        qkv_gemm<<<gQKV, 256, smemBF>>>(pyb, wqt, wkt, wvt);
        fattn_kernel<<<gAttn, 256, smemAttn>>>();
        resid_gemm<<<gProj, 256, smemBF>>>(pob, wot, h, bo + l * Dc, h);
        ln_kernel<<<Mrows, 128>>>(h, ln2g + l * Dc, ln2b + l * Dc, pyb);
        gelu_gemm<<<gProj, 256, smemBF>>>(pyb, w1t, ptb, b1 + l * Dc);
        resid_gemm<<<gProj, 256, smemBF>>>(ptb, w2t, h, b2 + l * Dc, h);
    }
}